// round 12
// baseline (speedup 1.0000x reference)
#include <cuda_runtime.h>
#include <cuda_fp16.h>
#include <math.h>

#define G 512
#define D 256
#define MAXN 204800
#define GRID_CAP 1184

// ---------------- device scratch ----------------
__device__ float    g_Wc[1024 * 512];
__device__ float    g_biasc[1024];
__device__ int      g_counts[G];            // zero-init; k_scan resets after use
__device__ int      g_cursor[G];
__device__ __align__(16) int g_perm[MAXN];
__device__ __align__(16) int g_grank[MAXN];
__device__ float    g_xbuf[G * 512];        // [h | r(unnormalized)]
__device__ float    g_cbuf[G * D];
__device__ float    g_gates[G * 1024];
__device__ unsigned g_gmaxe[G];
__device__ float    g_gsum[G];
__device__ __half2  g_feat16[MAXN * (D/2)];
__device__ int          g_bar_count;
__device__ volatile int g_bar_gen;

__device__ __forceinline__ unsigned h2_as_u32(__half2 h) {
    union { __half2 h; unsigned u; } c; c.h = h; return c.u;
}
__device__ __forceinline__ __half2 u32_as_h2(unsigned u) {
    union { unsigned u; __half2 h; } c; c.u = u; return c.h;
}
__device__ __forceinline__ unsigned fenc(float f) {
    unsigned u = __float_as_uint(f);
    return (u & 0x80000000u) ? ~u : (u | 0x80000000u);
}
__device__ __forceinline__ float fdec(unsigned u) {
    return (u & 0x80000000u) ? __uint_as_float(u ^ 0x80000000u)
                             : __uint_as_float(~u);
}
#define ENC_NEG_INF 0x007FFFFFu

__device__ __forceinline__ float sigf(float x) { return 1.0f / (1.0f + expf(-x)); }

// ---------------- cp.async helpers ----------------
__device__ __forceinline__ void cp16(void* sptr, const void* gptr) {
    unsigned saddr = (unsigned)__cvta_generic_to_shared(sptr);
    asm volatile("cp.async.cg.shared.global [%0], [%1], 16;" :: "r"(saddr), "l"(gptr) : "memory");
}
__device__ __forceinline__ void cp_commit() {
    asm volatile("cp.async.commit_group;" ::: "memory");
}
__device__ __forceinline__ void cp_wait1() {
    asm volatile("cp.async.wait_group 1;" ::: "memory");
}
__device__ __forceinline__ void cp_wait0() {
    asm volatile("cp.async.wait_group 0;" ::: "memory");
}

// ---------------- software grid barrier ----------------
__device__ __forceinline__ void grid_barrier() {
    __syncthreads();
    if (threadIdx.x == 0) {
        __threadfence();
        int gen = g_bar_gen;
        asm volatile("" ::: "memory");
        if (atomicAdd(&g_bar_count, 1) == (int)gridDim.x - 1) {
            g_bar_count = 0;
            __threadfence();
            atomicAdd((int*)&g_bar_gen, 1);
        } else {
            while (g_bar_gen == gen) __nanosleep(64);
        }
        __threadfence();
    }
    __syncthreads();
}

// ---------------- combined preamble ----------------
__global__ void __launch_bounds__(256) k_pre(const float* __restrict__ W_ih,
                                             const float* __restrict__ W_hh,
                                             const float* __restrict__ b_ih,
                                             const float* __restrict__ b_hh,
                                             const int* __restrict__ bidx, int N) {
    int b = blockIdx.x;
    if (b < 2048) {
        int i = b * 256 + threadIdx.x;
        int j = i >> 9, k = i & 511;
        float w = W_ih[i];
        if (k < D) w += W_hh[j * D + k];
        g_Wc[i] = w;
        if (i < 1024) g_biasc[i] = b_ih[i] + b_hh[i];
    } else if (b < 2560) {
        __shared__ int sh[G];
        for (int i = threadIdx.x; i < G; i += 256) sh[i] = 0;
        __syncthreads();
        for (int i = (b - 2048) * 256 + threadIdx.x; i < N; i += 512 * 256)
            atomicAdd(&sh[bidx[i]], 1);
        __syncthreads();
        for (int i = threadIdx.x; i < G; i += 256)
            if (sh[i]) atomicAdd(&g_counts[i], sh[i]);
    } else {                              // LSTM step 1 (zero state)
        int idx = (b - 2560) * 256 + threadIdx.x;
        int g = idx >> 8, d = idx & 255;
        float bi = b_ih[d]       + b_hh[d];
        float bg = b_ih[512 + d] + b_hh[512 + d];
        float bo = b_ih[768 + d] + b_hh[768 + d];
        float i_ = sigf(bi), gt = tanhf(bg), o_ = sigf(bo);
        float c = i_ * gt;
        float h = o_ * tanhf(c);
        g_cbuf[idx] = c;
        g_xbuf[g * 512 + d] = h;
        g_xbuf[g * 512 + D + d] = 0.0f;
        if (idx < G) { g_gmaxe[idx] = ENC_NEG_INF; g_gsum[idx] = 0.0f; }
#pragma unroll
        for (int k2 = 0; k2 < 4; k2++) g_gates[idx * 4 + k2] = 0.0f;
    }
}

__global__ void k_scan() {
    __shared__ int s[G];
    int t = threadIdx.x;
    s[t] = g_counts[t];
    __syncthreads();
    for (int o = 1; o < G; o <<= 1) {
        int v = 0;
        if (t >= o) v = s[t - o];
        __syncthreads();
        if (t >= o) s[t] += v;
        __syncthreads();
    }
    g_cursor[t] = s[t] - g_counts[t];
    g_counts[t] = 0;
}

#define SCHUNK 1024
__global__ void __launch_bounds__(256) k_scatter(const int* __restrict__ bidx, int N) {
    __shared__ int hist[G];
    int t = threadIdx.x;
    int b0 = blockIdx.x * SCHUNK;
    for (int i = t; i < G; i += 256) hist[i] = 0;
    __syncthreads();
#pragma unroll
    for (int k = 0; k < SCHUNK / 256; k++) {
        int i = b0 + k * 256 + t;
        if (i < N) atomicAdd(&hist[bidx[i]], 1);
    }
    __syncthreads();
    for (int gidx = t; gidx < G; gidx += 256) {
        int c = hist[gidx];
        if (c > 0) hist[gidx] = atomicAdd(&g_cursor[gidx], c);
    }
    __syncthreads();
#pragma unroll
    for (int k = 0; k < SCHUNK / 256; k++) {
        int i = b0 + k * 256 + t;
        if (i < N) {
            int g = bidx[i];
            int p = atomicAdd(&hist[g], 1);
            g_perm[p] = i;
            g_grank[p] = g;
        }
    }
}

// ---------------- online softmax machinery ----------------
__device__ __forceinline__ void load_q(int g, int lane, float* q) {
    const float4* qr = (const float4*)(g_xbuf + (size_t)g * 512);
    float4 q0 = qr[lane * 2], q1 = qr[lane * 2 + 1];
    q[0] = q0.x; q[1] = q0.y; q[2] = q0.z; q[3] = q0.w;
    q[4] = q1.x; q[5] = q1.y; q[6] = q1.z; q[7] = q1.w;
}

__device__ __forceinline__ void expand16(uint4 fv, float* f) {
    float2 f0 = __half22float2(u32_as_h2(fv.x));
    float2 f1 = __half22float2(u32_as_h2(fv.y));
    float2 f2 = __half22float2(u32_as_h2(fv.z));
    float2 f3 = __half22float2(u32_as_h2(fv.w));
    f[0] = f0.x; f[1] = f0.y; f[2] = f1.x; f[3] = f1.y;
    f[4] = f2.x; f[5] = f2.y; f[6] = f3.x; f[7] = f3.y;
}

__device__ __forceinline__ float dot8(const float* f, const float* q) {
    return f[0]*q[0] + f[1]*q[1] + f[2]*q[2] + f[3]*q[3]
         + f[4]*q[4] + f[5]*q[5] + f[6]*q[6] + f[7]*q[7];
}

__device__ __forceinline__ float wreduce(float v) {
#pragma unroll
    for (int o = 16; o; o >>= 1) v += __shfl_xor_sync(0xffffffffu, v, o);
    return v;
}

__device__ __forceinline__ void o_flush_global(int g, float m, float s,
                                               const float* acc, int lane) {
    float M = fdec(g_gmaxe[g]);
    float sc = __expf(m - M);
    float* base = g_xbuf + (size_t)g * 512 + D + lane * 8;
#pragma unroll
    for (int k = 0; k < 8; k++) atomicAdd(base + k, acc[k] * sc);
    if (lane == 0) atomicAdd(&g_gsum[g], s * sc);
}

// sole-owner interior segment: scale-invariant, no global-max rescale needed
__device__ __forceinline__ void o_flush_local(int g, float s, const float* acc, int lane) {
    float* base = g_xbuf + (size_t)g * 512 + D + lane * 8;
#pragma unroll
    for (int k = 0; k < 8; k++) atomicAdd(base + k, acc[k]);
    if (lane == 0) atomicAdd(&g_gsum[g], s);
}

__device__ __forceinline__ void o_update(float e, const float* f,
                                         float& m, float& s, float* acc) {
    if (e > m) {
        float sc = __expf(m - e);
        s *= sc;
#pragma unroll
        for (int k = 0; k < 8; k++) acc[k] *= sc;
        m = e;
    }
    float w = __expf(e - m);
    s += w;
#pragma unroll
    for (int k = 0; k < 8; k++) acc[k] += w * f[k];
}

// 4-aligned warp partitions so pack metadata reads can use int4
__device__ __forceinline__ void warp_range(int N, int gsize, int bid, int warp,
                                           int& ws, int& we) {
    int per = (((N + gsize - 1) / gsize) + 3) & ~3;
    int bs = bid * per;
    int be = min(bs + per, N);
    int sub = ((((per + 7) >> 3)) + 3) & ~3;
    ws = min(bs + warp * sub, be);
    we = min(ws + sub, be);
}

// Core attention loop. FIRST=1: gather fp32 via perm, emit fp16 cache (direct loads).
// FIRST=0: fp16 path with cp.async smem double-buffered packs (zero register cost MLP).
// pool layout: [0,8K) pacc spill; [8K,40K) pack buffers (FIRST=0 only).
template <int FIRST>
__device__ __forceinline__ void attn_core(const float* __restrict__ feat, int N, char* pool) {
    float* s_pacc = (float*)pool;                 // [8 warps][256]
    uint4* s_buf  = (uint4*)(pool + 8192);        // [8 warps][2 bufs][4 rows][32 lanes]
    int warp = threadIdx.x >> 5, lane = threadIdx.x & 31;
    int ws, we;
    warp_range(N, gridDim.x, blockIdx.x, warp, ws, we);
    bool valid = ws < we;

    int curg = 0, pg = -1;
    bool started_inside = false;
    float m = -1e30f, s = 0.0f, pm = 0.0f, ps = 0.0f;
    float acc[8] = {};
    float q[8];

    uint4* mybuf = s_buf + warp * 256;            // 2*4*32 uint4 per warp

    auto cvt_row = [&](int r, int n) -> uint4 {
        const float4* fr = (const float4*)(feat + (size_t)n * D);
        float4 a = fr[lane * 2], b = fr[lane * 2 + 1];
        uint4 o;
        o.x = h2_as_u32(__floats2half2_rn(a.x, a.y));
        o.y = h2_as_u32(__floats2half2_rn(a.z, a.w));
        o.z = h2_as_u32(__floats2half2_rn(b.x, b.y));
        o.w = h2_as_u32(__floats2half2_rn(b.z, b.w));
        ((uint4*)(g_feat16 + (size_t)r * (D / 2)))[lane] = o;
        return o;
    };

    auto prefetch = [&](int rr, int bufi) {
#pragma unroll
        for (int j = 0; j < 4; j++) {
            const char* gp = (const char*)(g_feat16 + (size_t)(rr + j) * (D / 2)) + lane * 16;
            cp16(mybuf + bufi * 128 + j * 32 + lane, gp);
        }
        cp_commit();
    };

    auto boundary = [&](int newg) {
        if (started_inside) {
            o_flush_local(curg, s, acc, lane);
        } else {
            pg = curg; pm = m; ps = s;
#pragma unroll
            for (int k = 0; k < 8; k++) s_pacc[warp * 256 + lane * 8 + k] = acc[k];
        }
        started_inside = true;
        m = -1e30f; s = 0.0f;
#pragma unroll
        for (int k = 0; k < 8; k++) acc[k] = 0.0f;
        curg = newg;
        load_q(newg, lane, q);
    };

    auto process = [&](const uint4* fv4, const int* g4) {
        bool uni = (g4[0] == curg) & (g4[1] == curg) & (g4[2] == curg) & (g4[3] == curg);
        if (uni) {
            float e4[4];
#pragma unroll
            for (int j = 0; j < 4; j++) {
                float f[8]; expand16(fv4[j], f);
                e4[j] = dot8(f, q);
            }
#pragma unroll
            for (int o = 16; o; o >>= 1)
#pragma unroll
                for (int j = 0; j < 4; j++)
                    e4[j] += __shfl_xor_sync(0xffffffffu, e4[j], o);
#pragma unroll
            for (int j = 0; j < 4; j++) {
                float f[8]; expand16(fv4[j], f);
                o_update(e4[j], f, m, s, acc);
            }
        } else {
#pragma unroll
            for (int j = 0; j < 4; j++) {
                if (g4[j] != curg) boundary(g4[j]);
                float f[8]; expand16(fv4[j], f);
                float e = wreduce(dot8(f, q));
                o_update(e, f, m, s, acc);
            }
        }
    };

    if (valid) {
        curg = g_grank[ws];
        load_q(curg, lane, q);
        int npack = (we - ws) >> 2;
        if (FIRST) {
            for (int p = 0; p < npack; p++) {
                int rr = ws + p * 4;
                int4 gv = *(const int4*)(g_grank + rr);
                int g4[4] = {gv.x, gv.y, gv.z, gv.w};
                int4 pv = *(const int4*)(g_perm + rr);
                int n4[4] = {pv.x, pv.y, pv.z, pv.w};
                uint4 fv4[4];
#pragma unroll
                for (int j = 0; j < 4; j++) fv4[j] = cvt_row(rr + j, n4[j]);
                process(fv4, g4);
            }
        } else {
            if (npack > 0) prefetch(ws, 0);
            for (int p = 0; p < npack; p++) {
                int rr = ws + p * 4;
                if (p + 1 < npack) { prefetch(rr + 4, (p + 1) & 1); cp_wait1(); }
                else               cp_wait0();
                int4 gv = *(const int4*)(g_grank + rr);
                int g4[4] = {gv.x, gv.y, gv.z, gv.w};
                uint4 fv4[4];
                uint4* src = mybuf + (p & 1) * 128;
#pragma unroll
                for (int j = 0; j < 4; j++) fv4[j] = src[j * 32 + lane];
                process(fv4, g4);
            }
        }
        // tail
        for (int r = ws + npack * 4; r < we; r++) {
            int grp = g_grank[r];
            uint4 fv;
            if (FIRST) fv = cvt_row(r, g_perm[r]);
            else       fv = ((const uint4*)(g_feat16 + (size_t)r * (D / 2)))[lane];
            if (grp != curg) boundary(grp);
            float f[8]; expand16(fv, f);
            float e = wreduce(dot8(f, q));
            o_update(e, f, m, s, acc);
        }
        if (lane == 0) {
            atomicMax(&g_gmaxe[curg], fenc(m));
            if (pg >= 0) atomicMax(&g_gmaxe[pg], fenc(pm));
        }
    }
    grid_barrier();
    if (valid) {
        o_flush_global(curg, m, s, acc, lane);
        if (pg >= 0) {
            float t[8];
#pragma unroll
            for (int k = 0; k < 8; k++) t[k] = s_pacc[warp * 256 + lane * 8 + k];
            o_flush_global(pg, pm, ps, t, lane);
        }
    }
}

// ---------------- attention step 1 ----------------
__global__ void __launch_bounds__(256, 4) k_attn0(const float* __restrict__ feat, int N) {
    __shared__ __align__(16) char pool[8192];
    attn_core<1>(feat, N, pool);
}

// ---------------- fused step: GEMM | cell | attention ----------------
#define BM 64
#define BN 64
#define BK 32
__global__ void __launch_bounds__(256, 4) k_step(int N) {
    __shared__ __align__(16) char pool[40960];
    // phase 0: GEMM gates += q_star @ Wc^T (512 tiles, grid-strided), norm folded
    {
        float (*As)[BM + 4] = (float(*)[BM + 4])pool;
        float (*Bs)[BN + 4] = (float(*)[BN + 4])(pool + sizeof(float) * BK * (BM + 4));
        int tid = threadIdx.x;
        int lr = tid >> 2;
        int lc = (tid & 3) * 8;
        int tm = (tid >> 4) * 4;
        int tn = (tid & 15) * 4;
        for (int tile = blockIdx.x; tile < 512; tile += gridDim.x) {
            int bn = (tile & 15) * BN;          // 16 N-tiles
            int bm = ((tile >> 4) & 7) * BM;    // 8 M-tiles
            int kz = tile >> 7;                 // 4 K-slices
            int k0 = kz * 128;
            float inv = 1.0f;
            if (kz >= 2) inv = 1.0f / (g_gsum[bm + lr] + 1e-16f);
            float acc[4][4] = {};
            for (int kt = 0; kt < 128; kt += BK) {
                const float4* ap = (const float4*)(g_xbuf + (size_t)(bm + lr) * 512 + k0 + kt + lc);
                float4 a0 = ap[0], a1 = ap[1];
                a0.x *= inv; a0.y *= inv; a0.z *= inv; a0.w *= inv;
                a1.x *= inv; a1.y *= inv; a1.z *= inv; a1.w *= inv;
                const float4* bp = (const float4*)(g_Wc + (size_t)(bn + lr) * 512 + k0 + kt + lc);
                float4 b0 = bp[0], b1 = bp[1];
                __syncthreads();
                As[lc + 0][lr] = a0.x; As[lc + 1][lr] = a0.y; As[lc + 2][lr] = a0.z; As[lc + 3][lr] = a0.w;
                As[lc + 4][lr] = a1.x; As[lc + 5][lr] = a1.y; As[lc + 6][lr] = a1.z; As[lc + 7][lr] = a1.w;
                Bs[lc + 0][lr] = b0.x; Bs[lc + 1][lr] = b0.y; Bs[lc + 2][lr] = b0.z; Bs[lc + 3][lr] = b0.w;
                Bs[lc + 4][lr] = b1.x; Bs[lc + 5][lr] = b1.y; Bs[lc + 6][lr] = b1.z; Bs[lc + 7][lr] = b1.w;
                __syncthreads();
#pragma unroll
                for (int k = 0; k < BK; k++) {
                    float4 av = *(const float4*)(&As[k][tm]);
                    float4 bv = *(const float4*)(&Bs[k][tn]);
                    float a[4] = {av.x, av.y, av.z, av.w};
                    float b[4] = {bv.x, bv.y, bv.z, bv.w};
#pragma unroll
                    for (int i = 0; i < 4; i++)
#pragma unroll
                        for (int j = 0; j < 4; j++) acc[i][j] += a[i] * b[j];
                }
            }
#pragma unroll
            for (int i = 0; i < 4; i++)
#pragma unroll
                for (int j = 0; j < 4; j++)
                    atomicAdd(&g_gates[(size_t)(bm + tm + i) * 1024 + bn + tn + j], acc[i][j]);
        }
    }
    grid_barrier();

    // phase 1: LSTM cell
    for (int idx = blockIdx.x * 256 + threadIdx.x; idx < G * D; idx += gridDim.x * 256) {
        int g = idx >> 8, d = idx & 255;
        int base = g * 1024;
        float gi = g_gates[base + d]       + g_biasc[d];
        float gf = g_gates[base + 256 + d] + g_biasc[256 + d];
        float gg = g_gates[base + 512 + d] + g_biasc[512 + d];
        float go = g_gates[base + 768 + d] + g_biasc[768 + d];
        float i_ = sigf(gi), f_ = sigf(gf), gt = tanhf(gg), o_ = sigf(go);
        float c = f_ * g_cbuf[idx] + i_ * gt;
        float h = o_ * tanhf(c);
        g_cbuf[idx] = c;
        g_xbuf[g * 512 + d] = h;
        g_xbuf[g * 512 + D + d] = 0.0f;
        g_gates[base + d] = 0.0f; g_gates[base + 256 + d] = 0.0f;
        g_gates[base + 512 + d] = 0.0f; g_gates[base + 768 + d] = 0.0f;
        if (idx < G) { g_gmaxe[idx] = ENC_NEG_INF; g_gsum[idx] = 0.0f; }
    }
    grid_barrier();

    // phase 2: attention (fp16, cp.async double-buffered)
    attn_core<0>(nullptr, N, pool);
}

// ---------------- copy result out (normalize r) ----------------
__global__ void k_copyout(float* __restrict__ out) {
    int i = blockIdx.x * blockDim.x + threadIdx.x;
    if (i < G * 512) {
        int g = i >> 9, d = i & 511;
        float v = g_xbuf[i];
        if (d >= D) v *= 1.0f / (g_gsum[g] + 1e-16f);
        out[i] = v;
    }
}

// ---------------- host launcher ----------------
extern "C" void kernel_launch(void* const* d_in, const int* in_sizes, int n_in,
                              void* d_out, int out_size) {
    const float* feat  = (const float*)d_in[0];
    const int*   bidx  = (const int*)d_in[1];
    const float* W_ih  = (const float*)d_in[2];
    const float* W_hh  = (const float*)d_in[3];
    const float* b_ih  = (const float*)d_in[4];
    const float* b_hh  = (const float*)d_in[5];
    float* out = (float*)d_out;

    int N = in_sizes[0] / D;

    int sms = 148, occ0 = 1, occ1 = 1;
    cudaDeviceGetAttribute(&sms, cudaDevAttrMultiProcessorCount, 0);
    cudaOccupancyMaxActiveBlocksPerMultiprocessor(&occ0, k_attn0, 256, 0);
    cudaOccupancyMaxActiveBlocksPerMultiprocessor(&occ1, k_step, 256, 0);
    if (occ0 < 1) occ0 = 1;
    if (occ1 < 1) occ1 = 1;
    int agrid0 = sms * occ0; if (agrid0 > GRID_CAP) agrid0 = GRID_CAP;
    int agrid1 = sms * occ1; if (agrid1 > GRID_CAP) agrid1 = GRID_CAP;

    k_pre<<<3072, 256>>>(W_ih, W_hh, b_ih, b_hh, bidx, N);
    k_scan<<<1, 512>>>();
    k_scatter<<<(N + SCHUNK - 1) / SCHUNK, 256>>>(bidx, N);

    k_attn0<<<agrid0, 256>>>(feat, N);
    k_step<<<agrid1, 256>>>(N);
    k_step<<<agrid1, 256>>>(N);
    k_copyout<<<(G * 512 + 255) / 256, 256>>>(out);
}

// round 13
// speedup vs baseline: 1.0268x; 1.0268x over previous
#include <cuda_runtime.h>
#include <cuda_fp16.h>
#include <math.h>

#define G 512
#define D 256
#define MAXN 204800
#define TPB 512                 // threads per persistent block (16 warps)
#define GRID_CAP 592

// ---------------- device scratch ----------------
__device__ float    g_Wc[1024 * 512];
__device__ float    g_biasc[1024];
__device__ int      g_counts[G];            // zero-init; k_scan resets after use
__device__ int      g_cursor[G];
__device__ __align__(16) int g_perm[MAXN];
__device__ __align__(16) int g_grank[MAXN];
__device__ float    g_xbuf[G * 512];        // [h | r(unnormalized)]
__device__ float    g_cbuf[G * D];
__device__ float    g_gates[G * 1024];
__device__ unsigned g_gmaxe[G];
__device__ float    g_gsum[G];
__device__ __half2  g_feat16[MAXN * (D/2)];
__device__ int          g_bar_count;
__device__ volatile int g_bar_gen;

__device__ __forceinline__ unsigned h2_as_u32(__half2 h) {
    union { __half2 h; unsigned u; } c; c.h = h; return c.u;
}
__device__ __forceinline__ __half2 u32_as_h2(unsigned u) {
    union { unsigned u; __half2 h; } c; c.u = u; return c.h;
}
__device__ __forceinline__ unsigned fenc(float f) {
    unsigned u = __float_as_uint(f);
    return (u & 0x80000000u) ? ~u : (u | 0x80000000u);
}
__device__ __forceinline__ float fdec(unsigned u) {
    return (u & 0x80000000u) ? __uint_as_float(u ^ 0x80000000u)
                             : __uint_as_float(~u);
}
#define ENC_NEG_INF 0x007FFFFFu

__device__ __forceinline__ float sigf(float x) { return 1.0f / (1.0f + expf(-x)); }

// ---------------- software grid barrier ----------------
__device__ __forceinline__ void grid_barrier() {
    __syncthreads();
    if (threadIdx.x == 0) {
        __threadfence();
        int gen = g_bar_gen;
        asm volatile("" ::: "memory");
        if (atomicAdd(&g_bar_count, 1) == (int)gridDim.x - 1) {
            g_bar_count = 0;
            __threadfence();
            atomicAdd((int*)&g_bar_gen, 1);
        } else {
            while (g_bar_gen == gen) __nanosleep(64);
        }
        __threadfence();
    }
    __syncthreads();
}

// ---------------- combined preamble ----------------
__global__ void __launch_bounds__(256) k_pre(const float* __restrict__ W_ih,
                                             const float* __restrict__ W_hh,
                                             const float* __restrict__ b_ih,
                                             const float* __restrict__ b_hh,
                                             const int* __restrict__ bidx, int N) {
    int b = blockIdx.x;
    if (b < 2048) {
        int i = b * 256 + threadIdx.x;
        int j = i >> 9, k = i & 511;
        float w = W_ih[i];
        if (k < D) w += W_hh[j * D + k];
        g_Wc[i] = w;
        if (i < 1024) g_biasc[i] = b_ih[i] + b_hh[i];
    } else if (b < 2560) {
        __shared__ int sh[G];
        for (int i = threadIdx.x; i < G; i += 256) sh[i] = 0;
        __syncthreads();
        for (int i = (b - 2048) * 256 + threadIdx.x; i < N; i += 512 * 256)
            atomicAdd(&sh[bidx[i]], 1);
        __syncthreads();
        for (int i = threadIdx.x; i < G; i += 256)
            if (sh[i]) atomicAdd(&g_counts[i], sh[i]);
    } else {                              // LSTM step 1 (zero state)
        int idx = (b - 2560) * 256 + threadIdx.x;
        int g = idx >> 8, d = idx & 255;
        float bi = b_ih[d]       + b_hh[d];
        float bg = b_ih[512 + d] + b_hh[512 + d];
        float bo = b_ih[768 + d] + b_hh[768 + d];
        float i_ = sigf(bi), gt = tanhf(bg), o_ = sigf(bo);
        float c = i_ * gt;
        float h = o_ * tanhf(c);
        g_cbuf[idx] = c;
        g_xbuf[g * 512 + d] = h;
        g_xbuf[g * 512 + D + d] = 0.0f;
        if (idx < G) { g_gmaxe[idx] = ENC_NEG_INF; g_gsum[idx] = 0.0f; }
#pragma unroll
        for (int k2 = 0; k2 < 4; k2++) g_gates[idx * 4 + k2] = 0.0f;
    }
}

__global__ void k_scan() {
    __shared__ int s[G];
    int t = threadIdx.x;
    s[t] = g_counts[t];
    __syncthreads();
    for (int o = 1; o < G; o <<= 1) {
        int v = 0;
        if (t >= o) v = s[t - o];
        __syncthreads();
        if (t >= o) s[t] += v;
        __syncthreads();
    }
    g_cursor[t] = s[t] - g_counts[t];
    g_counts[t] = 0;
}

#define SCHUNK 1024
__global__ void __launch_bounds__(256) k_scatter(const int* __restrict__ bidx, int N) {
    __shared__ int hist[G];
    int t = threadIdx.x;
    int b0 = blockIdx.x * SCHUNK;
    for (int i = t; i < G; i += 256) hist[i] = 0;
    __syncthreads();
#pragma unroll
    for (int k = 0; k < SCHUNK / 256; k++) {
        int i = b0 + k * 256 + t;
        if (i < N) atomicAdd(&hist[bidx[i]], 1);
    }
    __syncthreads();
    for (int gidx = t; gidx < G; gidx += 256) {
        int c = hist[gidx];
        if (c > 0) hist[gidx] = atomicAdd(&g_cursor[gidx], c);
    }
    __syncthreads();
#pragma unroll
    for (int k = 0; k < SCHUNK / 256; k++) {
        int i = b0 + k * 256 + t;
        if (i < N) {
            int g = bidx[i];
            int p = atomicAdd(&hist[g], 1);
            g_perm[p] = i;
            g_grank[p] = g;
        }
    }
}

// ---------------- online softmax machinery ----------------
__device__ __forceinline__ void load_q(int g, int lane, float* q) {
    const float4* qr = (const float4*)(g_xbuf + (size_t)g * 512);
    float4 q0 = qr[lane * 2], q1 = qr[lane * 2 + 1];
    q[0] = q0.x; q[1] = q0.y; q[2] = q0.z; q[3] = q0.w;
    q[4] = q1.x; q[5] = q1.y; q[6] = q1.z; q[7] = q1.w;
}

__device__ __forceinline__ void expand16(uint4 fv, float* f) {
    float2 f0 = __half22float2(u32_as_h2(fv.x));
    float2 f1 = __half22float2(u32_as_h2(fv.y));
    float2 f2 = __half22float2(u32_as_h2(fv.z));
    float2 f3 = __half22float2(u32_as_h2(fv.w));
    f[0] = f0.x; f[1] = f0.y; f[2] = f1.x; f[3] = f1.y;
    f[4] = f2.x; f[5] = f2.y; f[6] = f3.x; f[7] = f3.y;
}

__device__ __forceinline__ float dot8(const float* f, const float* q) {
    return f[0]*q[0] + f[1]*q[1] + f[2]*q[2] + f[3]*q[3]
         + f[4]*q[4] + f[5]*q[5] + f[6]*q[6] + f[7]*q[7];
}

__device__ __forceinline__ float wreduce(float v) {
#pragma unroll
    for (int o = 16; o; o >>= 1) v += __shfl_xor_sync(0xffffffffu, v, o);
    return v;
}

__device__ __forceinline__ void o_flush_global(int g, float m, float s,
                                               const float* acc, int lane) {
    float M = fdec(g_gmaxe[g]);
    float sc = __expf(m - M);
    float* base = g_xbuf + (size_t)g * 512 + D + lane * 8;
#pragma unroll
    for (int k = 0; k < 8; k++) atomicAdd(base + k, acc[k] * sc);
    if (lane == 0) atomicAdd(&g_gsum[g], s * sc);
}

// sole-owner interior segment: scale-invariant, no global-max rescale needed
__device__ __forceinline__ void o_flush_local(int g, float s, const float* acc, int lane) {
    float* base = g_xbuf + (size_t)g * 512 + D + lane * 8;
#pragma unroll
    for (int k = 0; k < 8; k++) atomicAdd(base + k, acc[k]);
    if (lane == 0) atomicAdd(&g_gsum[g], s);
}

__device__ __forceinline__ void o_update(float e, const float* f,
                                         float& m, float& s, float* acc) {
    if (e > m) {
        float sc = __expf(m - e);
        s *= sc;
#pragma unroll
        for (int k = 0; k < 8; k++) acc[k] *= sc;
        m = e;
    }
    float w = __expf(e - m);
    s += w;
#pragma unroll
    for (int k = 0; k < 8; k++) acc[k] += w * f[k];
}

// 4-aligned warp partitions (16 warps per block) so metadata reads can use int4
__device__ __forceinline__ void warp_range(int N, int gsize, int bid, int warp,
                                           int& ws, int& we) {
    int per = (((N + gsize - 1) / gsize) + 3) & ~3;
    int bs = bid * per;
    int be = min(bs + per, N);
    int sub = ((((per + 15) >> 4)) + 3) & ~3;
    ws = min(bs + warp * sub, be);
    we = min(ws + sub, be);
}

// Core attention loop. FIRST=1: gather fp32 via perm, emit fp16 cache.
// pool: pacc spill region, 16 warps x 256 floats = 16 KB.
template <int FIRST>
__device__ __forceinline__ void attn_core(const float* __restrict__ feat, int N, float* s_pacc) {
    int warp = threadIdx.x >> 5, lane = threadIdx.x & 31;
    int ws, we;
    warp_range(N, gridDim.x, blockIdx.x, warp, ws, we);
    bool valid = ws < we;

    int curg = 0, pg = -1;
    bool started_inside = false;
    float m = -1e30f, s = 0.0f, pm = 0.0f, ps = 0.0f;
    float acc[8] = {};
    float q[8];

    auto cvt_row = [&](int r, int n) -> uint4 {
        const float4* fr = (const float4*)(feat + (size_t)n * D);
        float4 a = fr[lane * 2], b = fr[lane * 2 + 1];
        uint4 o;
        o.x = h2_as_u32(__floats2half2_rn(a.x, a.y));
        o.y = h2_as_u32(__floats2half2_rn(a.z, a.w));
        o.z = h2_as_u32(__floats2half2_rn(b.x, b.y));
        o.w = h2_as_u32(__floats2half2_rn(b.z, b.w));
        ((uint4*)(g_feat16 + (size_t)r * (D / 2)))[lane] = o;
        return o;
    };

    auto boundary = [&](int newg) {
        if (started_inside) {
            o_flush_local(curg, s, acc, lane);
        } else {
            pg = curg; pm = m; ps = s;
#pragma unroll
            for (int k = 0; k < 8; k++) s_pacc[warp * 256 + lane * 8 + k] = acc[k];
        }
        started_inside = true;
        m = -1e30f; s = 0.0f;
#pragma unroll
        for (int k = 0; k < 8; k++) acc[k] = 0.0f;
        curg = newg;
        load_q(newg, lane, q);
    };

    if (valid) {
        curg = g_grank[ws];
        load_q(curg, lane, q);
        int r = ws;
        for (; r + 4 <= we; r += 4) {
            int4 gv = *(const int4*)(g_grank + r);
            int g4[4] = {gv.x, gv.y, gv.z, gv.w};
            uint4 fv4[4];
            if (FIRST) {
                int4 pv = *(const int4*)(g_perm + r);
                int n4[4] = {pv.x, pv.y, pv.z, pv.w};
#pragma unroll
                for (int j = 0; j < 4; j++) fv4[j] = cvt_row(r + j, n4[j]);
            } else {
#pragma unroll
                for (int j = 0; j < 4; j++)
                    fv4[j] = ((const uint4*)(g_feat16 + (size_t)(r + j) * (D / 2)))[lane];
            }
            bool uni = (g4[0] == curg) & (g4[1] == curg) & (g4[2] == curg) & (g4[3] == curg);
            if (uni) {
                float e4[4];
#pragma unroll
                for (int j = 0; j < 4; j++) {
                    float f[8]; expand16(fv4[j], f);
                    e4[j] = dot8(f, q);
                }
#pragma unroll
                for (int o = 16; o; o >>= 1)
#pragma unroll
                    for (int j = 0; j < 4; j++)
                        e4[j] += __shfl_xor_sync(0xffffffffu, e4[j], o);
#pragma unroll
                for (int j = 0; j < 4; j++) {
                    float f[8]; expand16(fv4[j], f);
                    o_update(e4[j], f, m, s, acc);
                }
            } else {
#pragma unroll
                for (int j = 0; j < 4; j++) {
                    if (g4[j] != curg) boundary(g4[j]);
                    float f[8]; expand16(fv4[j], f);
                    float e = wreduce(dot8(f, q));
                    o_update(e, f, m, s, acc);
                }
            }
        }
        for (; r < we; r++) {
            int grp = g_grank[r];
            uint4 fv;
            if (FIRST) fv = cvt_row(r, g_perm[r]);
            else       fv = ((const uint4*)(g_feat16 + (size_t)r * (D / 2)))[lane];
            if (grp != curg) boundary(grp);
            float f[8]; expand16(fv, f);
            float e = wreduce(dot8(f, q));
            o_update(e, f, m, s, acc);
        }
        if (lane == 0) {
            atomicMax(&g_gmaxe[curg], fenc(m));
            if (pg >= 0) atomicMax(&g_gmaxe[pg], fenc(pm));
        }
    }
    grid_barrier();
    if (valid) {
        o_flush_global(curg, m, s, acc, lane);
        if (pg >= 0) {
            float t[8];
#pragma unroll
            for (int k = 0; k < 8; k++) t[k] = s_pacc[warp * 256 + lane * 8 + k];
            o_flush_global(pg, pm, ps, t, lane);
        }
    }
}

// ---------------- attention step 1 ----------------
__global__ void __launch_bounds__(TPB, 2) k_attn0(const float* __restrict__ feat, int N) {
    __shared__ __align__(16) float s_pacc[16 * 256];
    attn_core<1>(feat, N, s_pacc);
}

// ---------------- fused step: GEMM | cell | attention ----------------
#define BM 64
#define BN 64
#define BK 32
// GEMM smem per 256-thread group: (BK*(BM+4) + BK*(BN+4)) floats = 17408 B; x2 groups
#define GEMM_SMEM_FLOATS (BK * (BM + 4) + BK * (BN + 4))

__global__ void __launch_bounds__(TPB, 2) k_step(int N) {
    __shared__ __align__(16) float pool[2 * GEMM_SMEM_FLOATS];  // 34816 B; pacc aliases front 16KB
    // phase 0: GEMM gates += q_star @ Wc^T (512 tiles), norm folded.
    // Two 256-thread groups per block handle independent tiles; uniform loop
    // count with guarded work keeps __syncthreads legal.
    {
        int grp = threadIdx.x >> 8;            // 0 or 1
        int tid = threadIdx.x & 255;
        float (*As)[BM + 4] = (float(*)[BM + 4])(pool + grp * GEMM_SMEM_FLOATS);
        float (*Bs)[BN + 4] = (float(*)[BN + 4])(pool + grp * GEMM_SMEM_FLOATS + BK * (BM + 4));
        int lr = tid >> 2;
        int lc = (tid & 3) * 8;
        int tm = (tid >> 4) * 4;
        int tn = (tid & 15) * 4;
        int stride = gridDim.x * 2;
        int P = (512 + stride - 1) / stride;
        for (int p = 0; p < P; p++) {
            int tile = blockIdx.x * 2 + grp + p * stride;
            bool live = tile < 512;
            int bn = 0, bm = 0, k0 = 0;
            float inv = 1.0f;
            if (live) {
                bn = (tile & 15) * BN;
                bm = ((tile >> 4) & 7) * BM;
                int kz = tile >> 7;
                k0 = kz * 128;
                if (kz >= 2) inv = 1.0f / (g_gsum[bm + lr] + 1e-16f);
            }
            float acc[4][4] = {};
            for (int kt = 0; kt < 128; kt += BK) {
                float4 a0 = {}, a1 = {}, b0 = {}, b1 = {};
                if (live) {
                    const float4* ap = (const float4*)(g_xbuf + (size_t)(bm + lr) * 512 + k0 + kt + lc);
                    a0 = ap[0]; a1 = ap[1];
                    a0.x *= inv; a0.y *= inv; a0.z *= inv; a0.w *= inv;
                    a1.x *= inv; a1.y *= inv; a1.z *= inv; a1.w *= inv;
                    const float4* bp = (const float4*)(g_Wc + (size_t)(bn + lr) * 512 + k0 + kt + lc);
                    b0 = bp[0]; b1 = bp[1];
                }
                __syncthreads();
                As[lc + 0][lr] = a0.x; As[lc + 1][lr] = a0.y; As[lc + 2][lr] = a0.z; As[lc + 3][lr] = a0.w;
                As[lc + 4][lr] = a1.x; As[lc + 5][lr] = a1.y; As[lc + 6][lr] = a1.z; As[lc + 7][lr] = a1.w;
                Bs[lc + 0][lr] = b0.x; Bs[lc + 1][lr] = b0.y; Bs[lc + 2][lr] = b0.z; Bs[lc + 3][lr] = b0.w;
                Bs[lc + 4][lr] = b1.x; Bs[lc + 5][lr] = b1.y; Bs[lc + 6][lr] = b1.z; Bs[lc + 7][lr] = b1.w;
                __syncthreads();
#pragma unroll
                for (int k = 0; k < BK; k++) {
                    float4 av = *(const float4*)(&As[k][tm]);
                    float4 bv = *(const float4*)(&Bs[k][tn]);
                    float a[4] = {av.x, av.y, av.z, av.w};
                    float b[4] = {bv.x, bv.y, bv.z, bv.w};
#pragma unroll
                    for (int i = 0; i < 4; i++)
#pragma unroll
                        for (int j = 0; j < 4; j++) acc[i][j] += a[i] * b[j];
                }
            }
            if (live) {
#pragma unroll
                for (int i = 0; i < 4; i++)
#pragma unroll
                    for (int j = 0; j < 4; j++)
                        atomicAdd(&g_gates[(size_t)(bm + tm + i) * 1024 + bn + tn + j], acc[i][j]);
            }
        }
    }
    grid_barrier();

    // phase 1: LSTM cell
    for (int idx = blockIdx.x * TPB + threadIdx.x; idx < G * D; idx += gridDim.x * TPB) {
        int g = idx >> 8, d = idx & 255;
        int base = g * 1024;
        float gi = g_gates[base + d]       + g_biasc[d];
        float gf = g_gates[base + 256 + d] + g_biasc[256 + d];
        float gg = g_gates[base + 512 + d] + g_biasc[512 + d];
        float go = g_gates[base + 768 + d] + g_biasc[768 + d];
        float i_ = sigf(gi), f_ = sigf(gf), gt = tanhf(gg), o_ = sigf(go);
        float c = f_ * g_cbuf[idx] + i_ * gt;
        float h = o_ * tanhf(c);
        g_cbuf[idx] = c;
        g_xbuf[g * 512 + d] = h;
        g_xbuf[g * 512 + D + d] = 0.0f;
        g_gates[base + d] = 0.0f; g_gates[base + 256 + d] = 0.0f;
        g_gates[base + 512 + d] = 0.0f; g_gates[base + 768 + d] = 0.0f;
        if (idx < G) { g_gmaxe[idx] = ENC_NEG_INF; g_gsum[idx] = 0.0f; }
    }
    grid_barrier();

    // phase 2: attention (fp16 path); pacc aliases pool front
    attn_core<0>(nullptr, N, pool);
}

// ---------------- copy result out (normalize r) ----------------
__global__ void k_copyout(float* __restrict__ out) {
    int i = blockIdx.x * blockDim.x + threadIdx.x;
    if (i < G * 512) {
        int g = i >> 9, d = i & 511;
        float v = g_xbuf[i];
        if (d >= D) v *= 1.0f / (g_gsum[g] + 1e-16f);
        out[i] = v;
    }
}

// ---------------- host launcher ----------------
extern "C" void kernel_launch(void* const* d_in, const int* in_sizes, int n_in,
                              void* d_out, int out_size) {
    const float* feat  = (const float*)d_in[0];
    const int*   bidx  = (const int*)d_in[1];
    const float* W_ih  = (const float*)d_in[2];
    const float* W_hh  = (const float*)d_in[3];
    const float* b_ih  = (const float*)d_in[4];
    const float* b_hh  = (const float*)d_in[5];
    float* out = (float*)d_out;

    int N = in_sizes[0] / D;

    int sms = 148, occ0 = 1, occ1 = 1;
    cudaDeviceGetAttribute(&sms, cudaDevAttrMultiProcessorCount, 0);
    cudaOccupancyMaxActiveBlocksPerMultiprocessor(&occ0, k_attn0, TPB, 0);
    cudaOccupancyMaxActiveBlocksPerMultiprocessor(&occ1, k_step, TPB, 0);
    if (occ0 < 1) occ0 = 1;
    if (occ1 < 1) occ1 = 1;
    int agrid0 = sms * occ0; if (agrid0 > GRID_CAP) agrid0 = GRID_CAP;
    int agrid1 = sms * occ1; if (agrid1 > GRID_CAP) agrid1 = GRID_CAP;

    k_pre<<<3072, 256>>>(W_ih, W_hh, b_ih, b_hh, bidx, N);
    k_scan<<<1, 512>>>();
    k_scatter<<<(N + SCHUNK - 1) / SCHUNK, 256>>>(bidx, N);

    k_attn0<<<agrid0, TPB>>>(feat, N);
    k_step<<<agrid1, TPB>>>(N);
    k_step<<<agrid1, TPB>>>(N);
    k_copyout<<<(G * 512 + 255) / 256, 256>>>(out);
}